// round 5
// baseline (speedup 1.0000x reference)
#include <cuda_runtime.h>

#define BSZv   16
#define DIMv   128
#define K1v    65537
#define NDATAv 1000000
#define CAPv   8
#define NOVFv  65536
#define NENTv  (BSZv * K1v)          // 1,048,592 = 262,148 * 4

static __device__ unsigned int g_counts[NDATAv + 4];   // [NDATAv] = overflow ctr
static __device__ unsigned int g_entries[(size_t)NDATAv * CAPv];
static __device__ unsigned int g_ovf[NOVFv];

__device__ __forceinline__ int detect_is64(const void* __restrict__ idx) {
    const long long* p = (const long long*)idx;
    #pragma unroll
    for (int i = 0; i < 4; i++) {
        long long v = p[i];
        if (v < 0 || v >= (long long)NDATAv) return 0;
    }
    return 1;
}

__device__ __forceinline__ long long load_index(const void* __restrict__ p,
                                                long long i, int is64) {
    return is64 ? ((const long long*)p)[i] : (long long)((const int*)p)[i];
}

__device__ __forceinline__ float warp_dot(float4 rv, float4 xv) {
    float a = rv.x * xv.x + rv.y * xv.y + rv.z * xv.z + rv.w * xv.w;
    #pragma unroll
    for (int off = 16; off >= 1; off >>= 1)
        a += __shfl_down_sync(0xffffffffu, a, off);
    return a;
}

// 4 entries per thread, vectorized index loads.
__global__ void __launch_bounds__(256) build_kernel(const void* __restrict__ y,
                                                    const void* __restrict__ idx) {
    __shared__ int s_is64;
    if (threadIdx.x == 0) s_is64 = detect_is64(idx);
    __syncthreads();
    const int is64 = s_is64;

    const long long e0 = ((long long)blockIdx.x * blockDim.x + threadIdx.x) * 4;
    if (e0 >= NENTv) return;

    long long rows[4];
    if (is64) {
        const longlong2 a = ((const longlong2*)idx)[e0 >> 1];
        const longlong2 b = ((const longlong2*)idx)[(e0 >> 1) + 1];
        rows[0] = a.x; rows[1] = a.y; rows[2] = b.x; rows[3] = b.y;
    } else {
        const int4 v = ((const int4*)idx)[e0 >> 2];
        rows[0] = v.x; rows[1] = v.y; rows[2] = v.z; rows[3] = v.w;
    }

    #pragma unroll
    for (int t = 0; t < 4; t++) {
        const long long e = e0 + t;
        const int b = (int)(e / K1v);
        const int k = (int)(e - (long long)b * K1v);
        long long row = rows[t];
        if (k == 0) row = load_index(y, b, is64);   // positive key slot

        const unsigned enc  = ((unsigned)b << 17) | (unsigned)k;
        const unsigned slot = atomicAdd(&g_counts[row], 1u);
        if (slot < CAPv) {
            g_entries[(size_t)row * CAPv + slot] = enc;
        } else {
            const unsigned o = atomicAdd(&g_counts[NDATAv], 1u);
            if (o < NOVFv) g_ovf[o] = enc;
        }
    }
}

// Streaming pass: copy bank -> out while computing every bucketed logit with
// the row already in registers. 4 rows/warp/iter, front-batched loads.
// Also re-zeros g_counts for the next graph replay.
__global__ void __launch_bounds__(256) main_kernel(
    const float* __restrict__ x, const float* __restrict__ memory,
    float* __restrict__ out)
{
    __shared__ float s_x[BSZv * DIMv];
    for (int i = threadIdx.x; i < BSZv * DIMv; i += blockDim.x) s_x[i] = x[i];
    __syncthreads();

    float* logits  = out;
    float* labels  = out + (long long)BSZv * K1v;
    float* out_mem = labels + BSZv;
    if (blockIdx.x == 0 && threadIdx.x < BSZv) labels[threadIdx.x] = 0.0f;

    const int lane = threadIdx.x & 31;
    const int warp = threadIdx.x >> 5;
    const float4* mem4 = (const float4*)memory;
    float4*       out4 = (float4*)out_mem;
    const float4* sx4  = (const float4*)s_x;
    const float t_inv  = 1.0f / 0.07f;

    const long long base0  = ((long long)blockIdx.x * 8 + warp) * 4;
    const long long stride = (long long)gridDim.x * 32;

    for (long long r0 = base0; r0 < NDATAv; r0 += stride) {
        // ---- front-batched loads: counts + entries + 4 rows (MLP ~9) ----
        const uint4 cnt4 = *(const uint4*)(g_counts + r0);
        uint4 ent[4];
        #pragma unroll
        for (int i = 0; i < 4; i++)
            ent[i] = *(const uint4*)(g_entries + (size_t)(r0 + i) * CAPv);
        float4 rv[4];
        #pragma unroll
        for (int i = 0; i < 4; i++)
            rv[i] = __ldcs(&mem4[(r0 + i) * 32 + lane]);

        // reset counts for the next call (invariant: counts==0 between calls)
        if (lane == 0)
            *(uint4*)(g_counts + r0) = make_uint4(0u, 0u, 0u, 0u);

        // ---- stream out (EMA rows patched later by tail_kernel) ----
        #pragma unroll
        for (int i = 0; i < 4; i++)
            __stcs(&out4[(r0 + i) * 32 + lane], rv[i]);

        const unsigned cnts[4] = {cnt4.x, cnt4.y, cnt4.z, cnt4.w};
        #pragma unroll
        for (int i = 0; i < 4; i++) {
            const unsigned c = cnts[i] > CAPv ? CAPv : cnts[i];
            if (c == 0) continue;
            const unsigned s0 = ent[i].x, s1 = ent[i].y, s2 = ent[i].z, s3 = ent[i].w;
            #pragma unroll
            for (int j = 0; j < 4; j++) {
                if (j < (int)c) {
                    const unsigned enc = (j == 0) ? s0 : (j == 1) ? s1
                                       : (j == 2) ? s2 : s3;
                    const int b = enc >> 17;
                    const int k = enc & 0x1FFFF;
                    const float a = warp_dot(rv[i], sx4[b * 32 + lane]);
                    if (lane == 0) logits[(long long)b * K1v + k] = a * t_inv;
                }
            }
            for (unsigned j = 4; j < c; j++) {          // rare (P ~ 2e-3/row)
                const unsigned enc = g_entries[(size_t)(r0 + i) * CAPv + j];
                const int b = enc >> 17;
                const int k = enc & 0x1FFFF;
                const float a = warp_dot(rv[i], sx4[b * 32 + lane]);
                if (lane == 0) logits[(long long)b * K1v + k] = a * t_inv;
            }
        }
    }
}

// Tail: block 0 = overflow logits (processes the WHOLE list, then resets the
// counter); block 1 = EMA-renormalize + scatter the 16 positive rows.
__global__ void __launch_bounds__(512) tail_kernel(
    const float* __restrict__ x, const void* __restrict__ y,
    const void* __restrict__ idx, const float* __restrict__ memory,
    float* __restrict__ out)
{
    __shared__ int s_is64;
    if (threadIdx.x == 0) s_is64 = detect_is64(idx);
    __syncthreads();
    const int is64 = s_is64;

    const int lane = threadIdx.x & 31;
    const int warp = threadIdx.x >> 5;

    if (blockIdx.x == 1) {
        // ---- EMA update of the 16 positive rows ----
        float* out_mem = out + (long long)BSZv * K1v + BSZv;
        if (warp < BSZv) {
            const long long row = load_index(y, warp, is64);
            const float4 mv = ((const float4*)memory)[row * 32 + lane];
            const float4 xv = ((const float4*)x)[warp * 32 + lane];
            float4 w = make_float4(0.5f * (mv.x + xv.x), 0.5f * (mv.y + xv.y),
                                   0.5f * (mv.z + xv.z), 0.5f * (mv.w + xv.w));
            float ss = w.x * w.x + w.y * w.y + w.z * w.z + w.w * w.w;
            #pragma unroll
            for (int off = 16; off >= 1; off >>= 1)
                ss += __shfl_xor_sync(0xffffffffu, ss, off);
            const float inv = 1.0f / fmaxf(sqrtf(ss), 1e-12f);
            w.x *= inv; w.y *= inv; w.z *= inv; w.w *= inv;
            ((float4*)out_mem)[row * 32 + lane] = w;
        }
        return;
    }

    // ---- block 0: overflow entries (normally n == 0) ----
    const unsigned n = min(g_counts[NDATAv], (unsigned)NOVFv);
    if (n > 0) {
        const float4* mem4 = (const float4*)memory;
        const float4* x4   = (const float4*)x;
        const float t_inv  = 1.0f / 0.07f;
        for (unsigned i = warp; i < n; i += blockDim.x >> 5) {
            const unsigned enc = g_ovf[i];
            const int b = enc >> 17;
            const int k = enc & 0x1FFFF;
            const long long e = (long long)b * K1v + k;
            const long long row = (k == 0) ? load_index(y, b, is64)
                                           : load_index(idx, e, is64);
            const float a = warp_dot(mem4[row * 32 + lane], x4[b * 32 + lane]);
            if (lane == 0) out[e] = a * t_inv;
        }
    }
    __syncthreads();
    if (threadIdx.x == 0) g_counts[NDATAv] = 0u;   // reset for next call
}

extern "C" void kernel_launch(void* const* d_in, const int* in_sizes, int n_in,
                              void* d_out, int out_size)
{
    const float* x      = (const float*)d_in[0];
    const void*  y      = d_in[1];
    const void*  idx    = d_in[2];
    const float* memory = (const float*)d_in[3];
    float*       out    = (float*)d_out;
    (void)in_sizes; (void)n_in; (void)out_size;

    build_kernel<<<(NENTv / 4 + 255) / 256, 256>>>(y, idx);
    main_kernel<<<4096, 256>>>(x, memory, out);
    tail_kernel<<<2, 512>>>(x, y, idx, memory, out);
}

// round 6
// speedup vs baseline: 2.1548x; 2.1548x over previous
#include <cuda_runtime.h>

#define BSZv   16
#define DIMv   128
#define K1v    65537
#define NDATAv 1000000
#define CAPv   8
#define NOVFv  65536
#define NENTv  (BSZv * K1v)          // 1,048,592 = 262,148 * 4

static __device__ unsigned int g_counts[NDATAv + 4];   // [NDATAv] = overflow ctr
static __device__ unsigned int g_entries[(size_t)NDATAv * CAPv];
static __device__ unsigned int g_ovf[NOVFv];

__device__ __forceinline__ int detect_is64(const void* __restrict__ idx) {
    const long long* p = (const long long*)idx;
    #pragma unroll
    for (int i = 0; i < 4; i++) {
        long long v = p[i];
        if (v < 0 || v >= (long long)NDATAv) return 0;
    }
    return 1;
}

__device__ __forceinline__ long long load_index(const void* __restrict__ p,
                                                long long i, int is64) {
    return is64 ? ((const long long*)p)[i] : (long long)((const int*)p)[i];
}

__device__ __forceinline__ float warp_dot(float4 rv, float4 xv) {
    float a = rv.x * xv.x + rv.y * xv.y + rv.z * xv.z + rv.w * xv.w;
    #pragma unroll
    for (int off = 16; off >= 1; off >>= 1)
        a += __shfl_down_sync(0xffffffffu, a, off);
    return a;
}

// Zero counts + overflow counter (16B vectorized).
__global__ void zero_kernel() {
    const unsigned q = blockIdx.x * blockDim.x + threadIdx.x;   // quad index
    if (q < (NDATAv + 4) / 4)
        ((uint4*)g_counts)[q] = make_uint4(0u, 0u, 0u, 0u);
}

// 4 entries per thread, vectorized index loads.
__global__ void __launch_bounds__(256) build_kernel(const void* __restrict__ y,
                                                    const void* __restrict__ idx) {
    __shared__ int s_is64;
    if (threadIdx.x == 0) s_is64 = detect_is64(idx);
    __syncthreads();
    const int is64 = s_is64;

    const long long e0 = ((long long)blockIdx.x * blockDim.x + threadIdx.x) * 4;
    if (e0 >= NENTv) return;

    long long rows[4];
    if (is64) {
        const longlong2 a = ((const longlong2*)idx)[e0 >> 1];
        const longlong2 b = ((const longlong2*)idx)[(e0 >> 1) + 1];
        rows[0] = a.x; rows[1] = a.y; rows[2] = b.x; rows[3] = b.y;
    } else {
        const int4 v = ((const int4*)idx)[e0 >> 2];
        rows[0] = v.x; rows[1] = v.y; rows[2] = v.z; rows[3] = v.w;
    }

    #pragma unroll
    for (int t = 0; t < 4; t++) {
        const long long e = e0 + t;
        const int b = (int)(e / K1v);
        const int k = (int)(e - (long long)b * K1v);
        long long row = rows[t];
        if (k == 0) row = load_index(y, b, is64);   // positive key slot

        const unsigned enc  = ((unsigned)b << 17) | (unsigned)k;
        const unsigned slot = atomicAdd(&g_counts[row], 1u);
        if (slot < CAPv) {
            g_entries[(size_t)row * CAPv + slot] = enc;
        } else {
            const unsigned o = atomicAdd(&g_counts[NDATAv], 1u);
            if (o < NOVFv) g_ovf[o] = enc;
        }
    }
}

// Streaming pass: copy bank -> out while computing every bucketed logit with
// the row already in registers. 4 rows/warp/iter, front-batched loads.
// NO stores to scratch globals here (aliasing store would serialize the MLP).
__global__ void __launch_bounds__(256) main_kernel(
    const float* __restrict__ x, const float* __restrict__ memory,
    float* __restrict__ out)
{
    __shared__ float s_x[BSZv * DIMv];
    for (int i = threadIdx.x; i < BSZv * DIMv; i += blockDim.x) s_x[i] = x[i];
    __syncthreads();

    float* logits  = out;
    float* labels  = out + (long long)BSZv * K1v;
    float* out_mem = labels + BSZv;
    if (blockIdx.x == 0 && threadIdx.x < BSZv) labels[threadIdx.x] = 0.0f;

    const int lane = threadIdx.x & 31;
    const int warp = threadIdx.x >> 5;
    const float4* mem4 = (const float4*)memory;
    float4*       out4 = (float4*)out_mem;
    const float4* sx4  = (const float4*)s_x;
    const float t_inv  = 1.0f / 0.07f;

    const long long base0  = ((long long)blockIdx.x * 8 + warp) * 4;
    const long long stride = (long long)gridDim.x * 32;

    for (long long r0 = base0; r0 < NDATAv; r0 += stride) {
        // ---- front-batched loads: counts + entries + 4 rows (MLP ~9) ----
        const uint4 cnt4 = *(const uint4*)(g_counts + r0);
        uint4 ent[4];
        #pragma unroll
        for (int i = 0; i < 4; i++)
            ent[i] = *(const uint4*)(g_entries + (size_t)(r0 + i) * CAPv);
        float4 rv[4];
        #pragma unroll
        for (int i = 0; i < 4; i++)
            rv[i] = __ldcs(&mem4[(r0 + i) * 32 + lane]);

        // ---- stream out (EMA rows patched later by tail_kernel) ----
        #pragma unroll
        for (int i = 0; i < 4; i++)
            __stcs(&out4[(r0 + i) * 32 + lane], rv[i]);

        const unsigned cnts[4] = {cnt4.x, cnt4.y, cnt4.z, cnt4.w};
        #pragma unroll
        for (int i = 0; i < 4; i++) {
            const unsigned c = cnts[i] > CAPv ? CAPv : cnts[i];
            if (c == 0) continue;
            const unsigned s0 = ent[i].x, s1 = ent[i].y, s2 = ent[i].z, s3 = ent[i].w;
            #pragma unroll
            for (int j = 0; j < 4; j++) {
                if (j < (int)c) {
                    const unsigned enc = (j == 0) ? s0 : (j == 1) ? s1
                                       : (j == 2) ? s2 : s3;
                    const int b = enc >> 17;
                    const int k = enc & 0x1FFFF;
                    const float a = warp_dot(rv[i], sx4[b * 32 + lane]);
                    if (lane == 0) logits[(long long)b * K1v + k] = a * t_inv;
                }
            }
            for (unsigned j = 4; j < c; j++) {          // rare (P ~ 2e-3/row)
                const unsigned enc = g_entries[(size_t)(r0 + i) * CAPv + j];
                const int b = enc >> 17;
                const int k = enc & 0x1FFFF;
                const float a = warp_dot(rv[i], sx4[b * 32 + lane]);
                if (lane == 0) logits[(long long)b * K1v + k] = a * t_inv;
            }
        }
    }
}

// Tail: block 0 = overflow logits (normally empty); block 1 = EMA rows.
__global__ void __launch_bounds__(512) tail_kernel(
    const float* __restrict__ x, const void* __restrict__ y,
    const void* __restrict__ idx, const float* __restrict__ memory,
    float* __restrict__ out)
{
    __shared__ int s_is64;
    if (threadIdx.x == 0) s_is64 = detect_is64(idx);
    __syncthreads();
    const int is64 = s_is64;

    const int lane = threadIdx.x & 31;
    const int warp = threadIdx.x >> 5;

    if (blockIdx.x == 1) {
        // ---- EMA update of the 16 positive rows ----
        float* out_mem = out + (long long)BSZv * K1v + BSZv;
        if (warp < BSZv) {
            const long long row = load_index(y, warp, is64);
            const float4 mv = ((const float4*)memory)[row * 32 + lane];
            const float4 xv = ((const float4*)x)[warp * 32 + lane];
            float4 w = make_float4(0.5f * (mv.x + xv.x), 0.5f * (mv.y + xv.y),
                                   0.5f * (mv.z + xv.z), 0.5f * (mv.w + xv.w));
            float ss = w.x * w.x + w.y * w.y + w.z * w.z + w.w * w.w;
            #pragma unroll
            for (int off = 16; off >= 1; off >>= 1)
                ss += __shfl_xor_sync(0xffffffffu, ss, off);
            const float inv = 1.0f / fmaxf(sqrtf(ss), 1e-12f);
            w.x *= inv; w.y *= inv; w.z *= inv; w.w *= inv;
            ((float4*)out_mem)[row * 32 + lane] = w;
        }
        return;
    }

    // ---- block 0: overflow entries (normally n == 0) ----
    const unsigned n = min(g_counts[NDATAv], (unsigned)NOVFv);
    if (n == 0) return;
    const float4* mem4 = (const float4*)memory;
    const float4* x4   = (const float4*)x;
    const float t_inv  = 1.0f / 0.07f;
    for (unsigned i = warp; i < n; i += blockDim.x >> 5) {
        const unsigned enc = g_ovf[i];
        const int b = enc >> 17;
        const int k = enc & 0x1FFFF;
        const long long e = (long long)b * K1v + k;
        const long long row = (k == 0) ? load_index(y, b, is64)
                                       : load_index(idx, e, is64);
        const float a = warp_dot(mem4[row * 32 + lane], x4[b * 32 + lane]);
        if (lane == 0) out[e] = a * t_inv;
    }
}

extern "C" void kernel_launch(void* const* d_in, const int* in_sizes, int n_in,
                              void* d_out, int out_size)
{
    const float* x      = (const float*)d_in[0];
    const void*  y      = d_in[1];
    const void*  idx    = d_in[2];
    const float* memory = (const float*)d_in[3];
    float*       out    = (float*)d_out;
    (void)in_sizes; (void)n_in; (void)out_size;

    zero_kernel<<<((NDATAv + 4) / 4 + 255) / 256, 256>>>();
    build_kernel<<<(NENTv / 4 + 255) / 256, 256>>>(y, idx);
    main_kernel<<<4096, 256>>>(x, memory, out);
    tail_kernel<<<2, 512>>>(x, y, idx, memory, out);
}